// round 5
// baseline (speedup 1.0000x reference)
#include <cuda_runtime.h>
#include <cstdint>

#define MROWS 8192
#define NCOLS 8192
#define DDIM  256
#define NTILES 64      // 8192 / 128
#define TOPK  256
#define KCAND 4096
#define NBINS 2048
#define BINSHIFT 13

// ---------------- static device scratch (no allocations allowed) ----------------
__device__ float        g_S[(size_t)MROWS * NCOLS];   // 256 MB: scores, then finalized scores (in place)
__device__ float        g_rowPart[NTILES * MROWS];    // per-column-tile partial row sums
__device__ float        g_colPart[NTILES * NCOLS];    // per-row-tile partial col sums
__device__ float        g_invRow[MROWS];
__device__ float        g_invCol[NCOLS];
__device__ unsigned int g_hist[NBINS];
__device__ unsigned int g_maxbits;
__device__ unsigned int g_count;
__device__ unsigned int g_thrbits;
__device__ unsigned int g_cand_bits[KCAND];
__device__ unsigned int g_cand_idx[KCAND];

// ---------------- init: reset per-replay state (graph replays!) ----------------
__global__ void init_kernel() {
    int t = blockIdx.x * blockDim.x + threadIdx.x;
    if (t < NBINS) g_hist[t] = 0;
    if (t == 0) { g_maxbits = 0u; g_count = 0u; g_thrbits = 0xFFFFFFFFu; }
}

// ---------------- GEMM + exp + partial sums ----------------
// C tile 128x128 per block, 256 threads, 8x8 register tile, K-chunks of 16.
__global__ void __launch_bounds__(256) gemm_exp_kernel(const float* __restrict__ A,
                                                       const float* __restrict__ B) {
    __shared__ float As[16][132];
    __shared__ float Bs[16][132];
    __shared__ float sC[16][128];

    const int tid = threadIdx.x;
    const int tx  = tid & 15;       // column group
    const int ty  = tid >> 4;       // row group
    const int rowBase = blockIdx.y * 128;
    const int colBase = blockIdx.x * 128;
    const int lr = tid >> 2;        // 0..63 : load row
    const int lc = (tid & 3) << 2;  // 0,4,8,12 : load col (k)

    float acc[8][8];
#pragma unroll
    for (int i = 0; i < 8; i++)
#pragma unroll
        for (int j = 0; j < 8; j++) acc[i][j] = 0.f;

    for (int k0 = 0; k0 < DDIM; k0 += 16) {
        float4 a0 = *(const float4*)(A + (size_t)(rowBase + lr)      * DDIM + k0 + lc);
        float4 a1 = *(const float4*)(A + (size_t)(rowBase + lr + 64) * DDIM + k0 + lc);
        float4 b0 = *(const float4*)(B + (size_t)(colBase + lr)      * DDIM + k0 + lc);
        float4 b1 = *(const float4*)(B + (size_t)(colBase + lr + 64) * DDIM + k0 + lc);
        __syncthreads();   // previous iter's reads done before overwrite
        As[lc+0][lr]    = a0.x; As[lc+1][lr]    = a0.y; As[lc+2][lr]    = a0.z; As[lc+3][lr]    = a0.w;
        As[lc+0][lr+64] = a1.x; As[lc+1][lr+64] = a1.y; As[lc+2][lr+64] = a1.z; As[lc+3][lr+64] = a1.w;
        Bs[lc+0][lr]    = b0.x; Bs[lc+1][lr]    = b0.y; Bs[lc+2][lr]    = b0.z; Bs[lc+3][lr]    = b0.w;
        Bs[lc+0][lr+64] = b1.x; Bs[lc+1][lr+64] = b1.y; Bs[lc+2][lr+64] = b1.z; Bs[lc+3][lr+64] = b1.w;
        __syncthreads();
#pragma unroll
        for (int kk = 0; kk < 16; kk++) {
            float a[8], b[8];
#pragma unroll
            for (int i = 0; i < 8; i++) a[i] = As[kk][ty * 8 + i];
#pragma unroll
            for (int j = 0; j < 8; j++) b[j] = Bs[kk][tx * 8 + j];
#pragma unroll
            for (int i = 0; i < 8; i++)
#pragma unroll
                for (int j = 0; j < 8; j++)
                    acc[i][j] = fmaf(a[i], b[j], acc[i][j]);
        }
    }

    // epilogue: s = exp(2*dot - 2), store, accumulate partial sums
    float rsum[8], csum[8];
#pragma unroll
    for (int i = 0; i < 8; i++) rsum[i] = 0.f;
#pragma unroll
    for (int j = 0; j < 8; j++) csum[j] = 0.f;

#pragma unroll
    for (int i = 0; i < 8; i++) {
        float sv[8];
#pragma unroll
        for (int j = 0; j < 8; j++) {
            float s = expf(fmaf(2.f, acc[i][j], -2.f));
            sv[j] = s;
            rsum[i] += s;
            csum[j] += s;
        }
        size_t base = (size_t)(rowBase + ty * 8 + i) * NCOLS + colBase + tx * 8;
        *(float4*)(g_S + base)     = make_float4(sv[0], sv[1], sv[2], sv[3]);
        *(float4*)(g_S + base + 4) = make_float4(sv[4], sv[5], sv[6], sv[7]);
    }

    // row partial sums: reduce across tx (same-ty threads are a half-warp)
#pragma unroll
    for (int i = 0; i < 8; i++) {
        float v = rsum[i];
#pragma unroll
        for (int off = 1; off < 16; off <<= 1)
            v += __shfl_xor_sync(0xFFFFFFFFu, v, off, 16);
        if (tx == 0)
            g_rowPart[blockIdx.x * MROWS + rowBase + ty * 8 + i] = v;
    }

    // column partial sums: reduce across ty via shared
#pragma unroll
    for (int j = 0; j < 8; j++) sC[ty][tx * 8 + j] = csum[j];
    __syncthreads();
    if (tid < 128) {
        float v = 0.f;
#pragma unroll
        for (int r = 0; r < 16; r++) v += sC[r][tid];
        g_colPart[blockIdx.y * NCOLS + colBase + tid] = v;
    }
}

// ---------------- deterministic reduction of partial sums -> reciprocals ----------------
__global__ void reduce_sums_kernel() {
    int i = blockIdx.x * blockDim.x + threadIdx.x;
    if (i < MROWS) {
        float s = 0.f;
        for (int b = 0; b < NTILES; b++) s += g_rowPart[b * MROWS + i];
        g_invRow[i] = 1.0f / s;
    } else if (i < MROWS + NCOLS) {
        int c = i - MROWS;
        float s = 0.f;
        for (int b = 0; b < NTILES; b++) s += g_colPart[b * NCOLS + c];
        g_invCol[c] = 1.0f / s;
    }
}

// ---------------- finalize: f = s*s*invRow*invCol (in place) + global max ----------------
__global__ void __launch_bounds__(256) finalize_kernel() {
    size_t base = (size_t)blockIdx.x * 4096;           // half a row per block
    int row = (int)(base >> 13);
    float invR = g_invRow[row];
    int jbase = (int)(base & 8191) + threadIdx.x * 16;
    size_t off = base + (size_t)threadIdx.x * 16;
    float fmaxv = 0.f;
#pragma unroll
    for (int q = 0; q < 4; q++) {
        float4 s  = *(float4*)(g_S + off + q * 4);
        float4 ic = *(const float4*)(g_invCol + jbase + q * 4);
        float4 f;
        f.x = s.x * s.x * invR * ic.x;
        f.y = s.y * s.y * invR * ic.y;
        f.z = s.z * s.z * invR * ic.z;
        f.w = s.w * s.w * invR * ic.w;
        *(float4*)(g_S + off + q * 4) = f;
        fmaxv = fmaxf(fmaxv, fmaxf(fmaxf(f.x, f.y), fmaxf(f.z, f.w)));
    }
    __shared__ float red[256];
    red[threadIdx.x] = fmaxv;
    __syncthreads();
    for (int s = 128; s > 0; s >>= 1) {
        if (threadIdx.x < s) red[threadIdx.x] = fmaxf(red[threadIdx.x], red[threadIdx.x + s]);
        __syncthreads();
    }
    if (threadIdx.x == 0) atomicMax(&g_maxbits, __float_as_uint(red[0]));
}

// ---------------- histogram of float-bit distance from max ----------------
__global__ void __launch_bounds__(256) hist_kernel() {
    __shared__ unsigned int h[NBINS];
    for (int t = threadIdx.x; t < NBINS; t += 256) h[t] = 0;
    __syncthreads();
    unsigned int mb = g_maxbits;
    size_t off = (size_t)blockIdx.x * 4096 + (size_t)threadIdx.x * 16;
#pragma unroll
    for (int q = 0; q < 4; q++) {
        float4 f = *(float4*)(g_S + off + q * 4);
        unsigned int d;
        d = mb - __float_as_uint(f.x); if (d < (NBINS << BINSHIFT)) atomicAdd(&h[d >> BINSHIFT], 1u);
        d = mb - __float_as_uint(f.y); if (d < (NBINS << BINSHIFT)) atomicAdd(&h[d >> BINSHIFT], 1u);
        d = mb - __float_as_uint(f.z); if (d < (NBINS << BINSHIFT)) atomicAdd(&h[d >> BINSHIFT], 1u);
        d = mb - __float_as_uint(f.w); if (d < (NBINS << BINSHIFT)) atomicAdd(&h[d >> BINSHIFT], 1u);
    }
    __syncthreads();
    for (int t = threadIdx.x; t < NBINS; t += 256)
        if (h[t]) atomicAdd(&g_hist[t], h[t]);
}

// ---------------- threshold scan ----------------
__global__ void threshold_kernel() {
    if (threadIdx.x == 0) {
        unsigned int cum = 0;
        int t = NBINS - 1;
        for (int b = 0; b < NBINS; b++) {
            cum += g_hist[b];
            if (cum >= TOPK) { t = b; break; }
        }
        g_thrbits = g_maxbits - (((unsigned int)(t + 1)) << BINSHIFT) + 1u;
    }
}

// ---------------- collect candidates above threshold ----------------
__global__ void __launch_bounds__(256) collect_kernel() {
    unsigned int thr = g_thrbits;
    size_t off = (size_t)blockIdx.x * 4096 + (size_t)threadIdx.x * 16;
#pragma unroll
    for (int q = 0; q < 4; q++) {
        float4 f = *(float4*)(g_S + off + q * 4);
        float vs[4] = {f.x, f.y, f.z, f.w};
#pragma unroll
        for (int e = 0; e < 4; e++) {
            unsigned int bits = __float_as_uint(vs[e]);
            if (bits >= thr) {
                unsigned int p = atomicAdd(&g_count, 1u);
                if (p < KCAND) {
                    g_cand_bits[p] = bits;
                    g_cand_idx[p]  = (unsigned int)(off + q * 4 + e);
                }
            }
        }
    }
}

// ---------------- single-block exact top-K by rank counting ----------------
__global__ void __launch_bounds__(1024) select_kernel(float* __restrict__ out) {
    __shared__ unsigned int sb[KCAND];
    __shared__ unsigned int si[KCAND];
    int n = (int)min(g_count, (unsigned int)KCAND);
    for (int i = threadIdx.x; i < n; i += 1024) {
        sb[i] = g_cand_bits[i];
        si[i] = g_cand_idx[i];
    }
    __syncthreads();
    for (int c = threadIdx.x; c < n; c += 1024) {
        unsigned int vb = sb[c], vi = si[c];
        int r = 0;
        for (int d = 0; d < n; d++) {
            unsigned int db = sb[d];
            r += (db > vb) || (db == vb && si[d] < vi);   // value desc, index asc (top_k tie-break)
        }
        if (r < TOPK) {
            out[r]            = (float)(vi >> 13);     // ref index = flat / 8192
            out[TOPK + r]     = (float)(vi & 8191u);   // src index = flat % 8192
            out[2 * TOPK + r] = __uint_as_float(vb);   // score
        }
    }
}

// ---------------- launch ----------------
extern "C" void kernel_launch(void* const* d_in, const int* in_sizes, int n_in,
                              void* d_out, int out_size) {
    const float* ref = (const float*)d_in[0];
    const float* src = (const float*)d_in[1];
    float* out = (float*)d_out;

    init_kernel<<<8, 256>>>();
    gemm_exp_kernel<<<dim3(64, 64), 256>>>(ref, src);
    reduce_sums_kernel<<<64, 256>>>();
    finalize_kernel<<<16384, 256>>>();
    hist_kernel<<<16384, 256>>>();
    threshold_kernel<<<1, 32>>>();
    collect_kernel<<<16384, 256>>>();
    select_kernel<<<1, 1024>>>(out);
}

// round 7
// speedup vs baseline: 1.3719x; 1.3719x over previous
#include <cuda_runtime.h>
#include <cstdint>

#define MROWS 8192
#define NCOLS 8192
#define DDIM  256
#define NTILES 64      // 8192 / 128
#define TOPK  256
#define KCAND 4096
#define NBINS 2048
#define BINSHIFT 13
#define SGRID 8192     // blocks for streaming passes
#define SITER 8        // float4s per thread per streaming pass

// ---------------- static device scratch (no allocations allowed) ----------------
__device__ float        g_S[(size_t)MROWS * NCOLS];   // 256 MB: raw scores s = exp(2d-2); never overwritten
__device__ float        g_rowPart[NTILES * MROWS];    // per-column-tile partial row sums
__device__ float        g_colPart[NTILES * NCOLS];    // per-row-tile partial col sums
__device__ float        g_invRow[MROWS];
__device__ float        g_invCol[NCOLS];
__device__ unsigned int g_hist[NBINS];
__device__ unsigned int g_maxbits;
__device__ unsigned int g_count;
__device__ unsigned int g_thrbits;
__device__ unsigned int g_cand_bits[KCAND];
__device__ unsigned int g_cand_idx[KCAND];

// ---------------- init: reset per-replay state (graph replays!) ----------------
__global__ void init_kernel() {
    int t = blockIdx.x * blockDim.x + threadIdx.x;
    if (t < NBINS) g_hist[t] = 0;
    if (t == 0) { g_maxbits = 0u; g_count = 0u; g_thrbits = 0xFFFFFFFFu; }
}

// ---------------- GEMM + exp + partial sums ----------------
// C tile 128x128 per block, 256 threads, 8x8 register tile in 4+4 z-pattern,
// K-chunks of 16. Operand fetch = 2x LDS.128 per array (conflict-free).
__global__ void __launch_bounds__(256) gemm_exp_kernel(const float* __restrict__ A,
                                                       const float* __restrict__ B) {
    __shared__ float As[16][132];
    __shared__ float Bs[16][132];
    __shared__ float sC[16][128];

    const int tid = threadIdx.x;
    const int tx  = tid & 15;       // column group (owns cols tx*4..+3 and 64+tx*4..+3)
    const int ty  = tid >> 4;       // row group    (owns rows ty*4..+3 and 64+ty*4..+3)
    const int rowBase = blockIdx.y * 128;
    const int colBase = blockIdx.x * 128;
    const int lr = tid >> 2;        // 0..63 : load row
    const int lc = (tid & 3) << 2;  // 0,4,8,12 : load col (k)

    float acc[8][8];
#pragma unroll
    for (int i = 0; i < 8; i++)
#pragma unroll
        for (int j = 0; j < 8; j++) acc[i][j] = 0.f;

    for (int k0 = 0; k0 < DDIM; k0 += 16) {
        float4 a0 = *(const float4*)(A + (size_t)(rowBase + lr)      * DDIM + k0 + lc);
        float4 a1 = *(const float4*)(A + (size_t)(rowBase + lr + 64) * DDIM + k0 + lc);
        float4 b0 = *(const float4*)(B + (size_t)(colBase + lr)      * DDIM + k0 + lc);
        float4 b1 = *(const float4*)(B + (size_t)(colBase + lr + 64) * DDIM + k0 + lc);
        __syncthreads();   // previous iter's reads done before overwrite
        As[lc+0][lr]    = a0.x; As[lc+1][lr]    = a0.y; As[lc+2][lr]    = a0.z; As[lc+3][lr]    = a0.w;
        As[lc+0][lr+64] = a1.x; As[lc+1][lr+64] = a1.y; As[lc+2][lr+64] = a1.z; As[lc+3][lr+64] = a1.w;
        Bs[lc+0][lr]    = b0.x; Bs[lc+1][lr]    = b0.y; Bs[lc+2][lr]    = b0.z; Bs[lc+3][lr]    = b0.w;
        Bs[lc+0][lr+64] = b1.x; Bs[lc+1][lr+64] = b1.y; Bs[lc+2][lr+64] = b1.z; Bs[lc+3][lr+64] = b1.w;
        __syncthreads();
#pragma unroll
        for (int kk = 0; kk < 16; kk++) {
            float4 aL = *(const float4*)&As[kk][ty * 4];
            float4 aH = *(const float4*)&As[kk][64 + ty * 4];
            float4 bL = *(const float4*)&Bs[kk][tx * 4];
            float4 bH = *(const float4*)&Bs[kk][64 + tx * 4];
            float a[8] = {aL.x, aL.y, aL.z, aL.w, aH.x, aH.y, aH.z, aH.w};
            float b[8] = {bL.x, bL.y, bL.z, bL.w, bH.x, bH.y, bH.z, bH.w};
#pragma unroll
            for (int i = 0; i < 8; i++)
#pragma unroll
                for (int j = 0; j < 8; j++)
                    acc[i][j] = fmaf(a[i], b[j], acc[i][j]);
        }
    }

    // epilogue: s = exp(2*dot - 2), store, accumulate partial sums
    float rsum[8], csum[8];
#pragma unroll
    for (int i = 0; i < 8; i++) rsum[i] = 0.f;
#pragma unroll
    for (int j = 0; j < 8; j++) csum[j] = 0.f;

#pragma unroll
    for (int i = 0; i < 8; i++) {
        const int ri = rowBase + ((i < 4) ? (ty * 4 + i) : (64 + ty * 4 + i - 4));
        float sv[8];
#pragma unroll
        for (int j = 0; j < 8; j++) {
            float s = expf(fmaf(2.f, acc[i][j], -2.f));
            sv[j] = s;
            rsum[i] += s;
            csum[j] += s;
        }
        size_t rb = (size_t)ri * NCOLS + colBase;
        *(float4*)(g_S + rb + tx * 4)      = make_float4(sv[0], sv[1], sv[2], sv[3]);
        *(float4*)(g_S + rb + 64 + tx * 4) = make_float4(sv[4], sv[5], sv[6], sv[7]);
    }

    // row partial sums: reduce across tx (same-ty threads are a half-warp)
#pragma unroll
    for (int i = 0; i < 8; i++) {
        float v = rsum[i];
#pragma unroll
        for (int off = 1; off < 16; off <<= 1)
            v += __shfl_xor_sync(0xFFFFFFFFu, v, off, 16);
        if (tx == 0) {
            const int ri = rowBase + ((i < 4) ? (ty * 4 + i) : (64 + ty * 4 + i - 4));
            g_rowPart[blockIdx.x * MROWS + ri] = v;
        }
    }

    // column partial sums: reduce across ty via shared
#pragma unroll
    for (int j = 0; j < 8; j++) {
        const int cj = (j < 4) ? (tx * 4 + j) : (64 + tx * 4 + j - 4);
        sC[ty][cj] = csum[j];
    }
    __syncthreads();
    if (tid < 128) {
        float v = 0.f;
#pragma unroll
        for (int r = 0; r < 16; r++) v += sC[r][tid];
        g_colPart[blockIdx.y * NCOLS + colBase + tid] = v;
    }
}

// ---------------- deterministic reduction of partial sums -> reciprocals ----------------
__global__ void reduce_sums_kernel() {
    int i = blockIdx.x * blockDim.x + threadIdx.x;
    if (i < MROWS) {
        float s = 0.f;
        for (int b = 0; b < NTILES; b++) s += g_rowPart[b * MROWS + i];
        g_invRow[i] = 1.0f / s;
    } else if (i < MROWS + NCOLS) {
        int c = i - MROWS;
        float s = 0.f;
        for (int b = 0; b < NTILES; b++) s += g_colPart[b * NCOLS + c];
        g_invCol[c] = 1.0f / s;
    }
}

// f = s*s*invR*invC, identical expression in every pass (bit-consistent).
__device__ __forceinline__ float4 fval4(float4 s, float invR, float4 ic) {
    float4 f;
    f.x = s.x * s.x * invR * ic.x;
    f.y = s.y * s.y * invR * ic.y;
    f.z = s.z * s.z * invR * ic.z;
    f.w = s.w * s.w * invR * ic.w;
    return f;
}

// ---------------- pass A: global max of f (read-only, coalesced, MLP=8) ----------------
__global__ void __launch_bounds__(256) max_kernel() {
    const float4* __restrict__ S4 = (const float4*)g_S;
    const float4* __restrict__ IC = (const float4*)g_invCol;
    size_t p0 = (size_t)blockIdx.x * 256 + threadIdx.x;
    float m = 0.f;
#pragma unroll
    for (int it = 0; it < SITER; it++) {
        size_t p = p0 + (size_t)it * (SGRID * 256);
        float4 s  = S4[p];
        float invR = g_invRow[p >> 11];       // 2048 float4 per row
        float4 ic = IC[p & 2047];
        float4 f = fval4(s, invR, ic);
        m = fmaxf(m, fmaxf(fmaxf(f.x, f.y), fmaxf(f.z, f.w)));
    }
    __shared__ float red[256];
    red[threadIdx.x] = m;
    __syncthreads();
    for (int s = 128; s > 0; s >>= 1) {
        if (threadIdx.x < s) red[threadIdx.x] = fmaxf(red[threadIdx.x], red[threadIdx.x + s]);
        __syncthreads();
    }
    if (threadIdx.x == 0) atomicMax(&g_maxbits, __float_as_uint(red[0]));
}

// ---------------- pass B: histogram of float-bit distance from max ----------------
__global__ void __launch_bounds__(256) hist_kernel() {
    __shared__ unsigned int h[NBINS];
    for (int t = threadIdx.x; t < NBINS; t += 256) h[t] = 0;
    __syncthreads();
    unsigned int mb = g_maxbits;
    const float4* __restrict__ S4 = (const float4*)g_S;
    const float4* __restrict__ IC = (const float4*)g_invCol;
    size_t p0 = (size_t)blockIdx.x * 256 + threadIdx.x;
#pragma unroll
    for (int it = 0; it < SITER; it++) {
        size_t p = p0 + (size_t)it * (SGRID * 256);
        float4 s  = S4[p];
        float invR = g_invRow[p >> 11];
        float4 ic = IC[p & 2047];
        float4 f = fval4(s, invR, ic);
        unsigned int d;
        d = mb - __float_as_uint(f.x); if (d < (NBINS << BINSHIFT)) atomicAdd(&h[d >> BINSHIFT], 1u);
        d = mb - __float_as_uint(f.y); if (d < (NBINS << BINSHIFT)) atomicAdd(&h[d >> BINSHIFT], 1u);
        d = mb - __float_as_uint(f.z); if (d < (NBINS << BINSHIFT)) atomicAdd(&h[d >> BINSHIFT], 1u);
        d = mb - __float_as_uint(f.w); if (d < (NBINS << BINSHIFT)) atomicAdd(&h[d >> BINSHIFT], 1u);
    }
    __syncthreads();
    for (int t = threadIdx.x; t < NBINS; t += 256)
        if (h[t]) atomicAdd(&g_hist[t], h[t]);
}

// ---------------- threshold scan ----------------
__global__ void threshold_kernel() {
    if (threadIdx.x == 0) {
        unsigned int cum = 0;
        int t = NBINS - 1;
        for (int b = 0; b < NBINS; b++) {
            cum += g_hist[b];
            if (cum >= TOPK) { t = b; break; }
        }
        g_thrbits = g_maxbits - (((unsigned int)(t + 1)) << BINSHIFT) + 1u;
    }
}

// ---------------- pass C: collect candidates above threshold ----------------
__global__ void __launch_bounds__(256) collect_kernel() {
    unsigned int thr = g_thrbits;
    const float4* __restrict__ S4 = (const float4*)g_S;
    const float4* __restrict__ IC = (const float4*)g_invCol;
    size_t p0 = (size_t)blockIdx.x * 256 + threadIdx.x;
#pragma unroll
    for (int it = 0; it < SITER; it++) {
        size_t p = p0 + (size_t)it * (SGRID * 256);
        float4 s  = S4[p];
        float invR = g_invRow[p >> 11];
        float4 ic = IC[p & 2047];
        float4 f = fval4(s, invR, ic);
        float vs[4] = {f.x, f.y, f.z, f.w};
#pragma unroll
        for (int e = 0; e < 4; e++) {
            unsigned int bits = __float_as_uint(vs[e]);
            if (bits >= thr) {
                unsigned int q = atomicAdd(&g_count, 1u);
                if (q < KCAND) {
                    g_cand_bits[q] = bits;
                    g_cand_idx[q]  = (unsigned int)(p * 4 + e);
                }
            }
        }
    }
}

// ---------------- single-block exact top-K by rank counting ----------------
__global__ void __launch_bounds__(1024) select_kernel(float* __restrict__ out) {
    __shared__ unsigned int sb[KCAND];
    __shared__ unsigned int si[KCAND];
    int n = (int)min(g_count, (unsigned int)KCAND);
    for (int i = threadIdx.x; i < n; i += 1024) {
        sb[i] = g_cand_bits[i];
        si[i] = g_cand_idx[i];
    }
    __syncthreads();
    for (int c = threadIdx.x; c < n; c += 1024) {
        unsigned int vb = sb[c], vi = si[c];
        int r = 0;
        for (int d = 0; d < n; d++) {
            unsigned int db = sb[d];
            r += (db > vb) || (db == vb && si[d] < vi);   // value desc, index asc (top_k tie-break)
        }
        if (r < TOPK) {
            out[r]            = (float)(vi >> 13);     // ref index = flat / 8192
            out[TOPK + r]     = (float)(vi & 8191u);   // src index = flat % 8192
            out[2 * TOPK + r] = __uint_as_float(vb);   // score
        }
    }
}

// ---------------- launch ----------------
extern "C" void kernel_launch(void* const* d_in, const int* in_sizes, int n_in,
                              void* d_out, int out_size) {
    const float* ref = (const float*)d_in[0];
    const float* src = (const float*)d_in[1];
    float* out = (float*)d_out;

    init_kernel<<<8, 256>>>();
    gemm_exp_kernel<<<dim3(64, 64), 256>>>(ref, src);
    reduce_sums_kernel<<<64, 256>>>();
    max_kernel<<<SGRID, 256>>>();
    hist_kernel<<<SGRID, 256>>>();
    threshold_kernel<<<1, 32>>>();
    collect_kernel<<<SGRID, 256>>>();
    select_kernel<<<1, 1024>>>(out);
}

// round 8
// speedup vs baseline: 1.5906x; 1.1595x over previous
#include <cuda_runtime.h>
#include <cstdint>

#define MROWS 8192
#define NCOLS 8192
#define DDIM  256
#define NTILES 64      // 8192 / 128
#define TOPK  256
#define KCAND 4096
#define NBINS 2048
#define BINSHIFT 13
#define SGRID 8192     // blocks for streaming passes
#define SITER 8        // float4s per thread per streaming pass

// ---------------- static device scratch (no allocations allowed) ----------------
__device__ float        g_S[(size_t)MROWS * NCOLS];   // 256 MB: raw scores s = exp(2d-2); never overwritten
__device__ float        g_rowPart[NTILES * MROWS];    // per-column-tile partial row sums
__device__ float        g_colPart[NTILES * NCOLS];    // per-row-tile partial col sums
__device__ float        g_invRow[MROWS];
__device__ float        g_invCol[NCOLS];
__device__ unsigned int g_hist[NBINS];
__device__ unsigned int g_maxbits;
__device__ unsigned int g_count;
__device__ unsigned int g_thrbits;
__device__ unsigned int g_cand_bits[KCAND];
__device__ unsigned int g_cand_idx[KCAND];

// ---------------- init: reset per-replay state (graph replays!) ----------------
__global__ void init_kernel() {
    int t = blockIdx.x * blockDim.x + threadIdx.x;
    if (t < NBINS) g_hist[t] = 0;
    if (t == 0) { g_maxbits = 0u; g_count = 0u; g_thrbits = 0xFFFFFFFFu; }
}

// ---------------- GEMM + exp + partial sums (double-buffered) ----------------
// C tile 128x128 per block, 256 threads, 8x8 register tile in 4+4 z-pattern.
// 2-stage smem pipeline: global loads for chunk c+1 overlap the FMA block of
// chunk c; ONE __syncthreads per chunk (the barrier at end of chunk c-1 proves
// all reads of the buffer overwritten at chunk c are complete).
__global__ void __launch_bounds__(256, 2) gemm_exp_kernel(const float* __restrict__ A,
                                                          const float* __restrict__ B) {
    __shared__ float As[2][16][132];
    __shared__ float Bs[2][16][132];
    __shared__ float sC[16][128];

    const int tid = threadIdx.x;
    const int tx  = tid & 15;       // column group (owns cols tx*4..+3 and 64+tx*4..+3)
    const int ty  = tid >> 4;       // row group    (owns rows ty*4..+3 and 64+ty*4..+3)
    const int rowBase = blockIdx.y * 128;
    const int colBase = blockIdx.x * 128;
    const int lr = tid >> 2;        // 0..63 : load row
    const int lc = (tid & 3) << 2;  // 0,4,8,12 : load col (k)

    const float* pA0 = A + (size_t)(rowBase + lr)      * DDIM + lc;
    const float* pA1 = A + (size_t)(rowBase + lr + 64) * DDIM + lc;
    const float* pB0 = B + (size_t)(colBase + lr)      * DDIM + lc;
    const float* pB1 = B + (size_t)(colBase + lr + 64) * DDIM + lc;

    float acc[8][8];
#pragma unroll
    for (int i = 0; i < 8; i++)
#pragma unroll
        for (int j = 0; j < 8; j++) acc[i][j] = 0.f;

    // prologue: load chunk 0 and stage into buffer 0
    float4 a0 = *(const float4*)pA0;
    float4 a1 = *(const float4*)pA1;
    float4 b0 = *(const float4*)pB0;
    float4 b1 = *(const float4*)pB1;
    As[0][lc+0][lr]    = a0.x; As[0][lc+1][lr]    = a0.y; As[0][lc+2][lr]    = a0.z; As[0][lc+3][lr]    = a0.w;
    As[0][lc+0][lr+64] = a1.x; As[0][lc+1][lr+64] = a1.y; As[0][lc+2][lr+64] = a1.z; As[0][lc+3][lr+64] = a1.w;
    Bs[0][lc+0][lr]    = b0.x; Bs[0][lc+1][lr]    = b0.y; Bs[0][lc+2][lr]    = b0.z; Bs[0][lc+3][lr]    = b0.w;
    Bs[0][lc+0][lr+64] = b1.x; Bs[0][lc+1][lr+64] = b1.y; Bs[0][lc+2][lr+64] = b1.z; Bs[0][lc+3][lr+64] = b1.w;
    __syncthreads();

#pragma unroll 1
    for (int c = 0; c < 16; ++c) {
        const int cur = c & 1;
        if (c < 15) {                       // issue next chunk's global loads early
            const int off = (c + 1) * 16;
            a0 = *(const float4*)(pA0 + off);
            a1 = *(const float4*)(pA1 + off);
            b0 = *(const float4*)(pB0 + off);
            b1 = *(const float4*)(pB1 + off);
        }
        const float (*cAs)[132] = As[cur];
        const float (*cBs)[132] = Bs[cur];
#pragma unroll
        for (int kk = 0; kk < 16; kk++) {
            float4 aL = *(const float4*)&cAs[kk][ty * 4];
            float4 aH = *(const float4*)&cAs[kk][64 + ty * 4];
            float4 bL = *(const float4*)&cBs[kk][tx * 4];
            float4 bH = *(const float4*)&cBs[kk][64 + tx * 4];
            float a[8] = {aL.x, aL.y, aL.z, aL.w, aH.x, aH.y, aH.z, aH.w};
            float b[8] = {bL.x, bL.y, bL.z, bL.w, bH.x, bH.y, bH.z, bH.w};
#pragma unroll
            for (int i = 0; i < 8; i++)
#pragma unroll
                for (int j = 0; j < 8; j++)
                    acc[i][j] = fmaf(a[i], b[j], acc[i][j]);
        }
        if (c < 15) {
            const int nxt = cur ^ 1;
            As[nxt][lc+0][lr]    = a0.x; As[nxt][lc+1][lr]    = a0.y; As[nxt][lc+2][lr]    = a0.z; As[nxt][lc+3][lr]    = a0.w;
            As[nxt][lc+0][lr+64] = a1.x; As[nxt][lc+1][lr+64] = a1.y; As[nxt][lc+2][lr+64] = a1.z; As[nxt][lc+3][lr+64] = a1.w;
            Bs[nxt][lc+0][lr]    = b0.x; Bs[nxt][lc+1][lr]    = b0.y; Bs[nxt][lc+2][lr]    = b0.z; Bs[nxt][lc+3][lr]    = b0.w;
            Bs[nxt][lc+0][lr+64] = b1.x; Bs[nxt][lc+1][lr+64] = b1.y; Bs[nxt][lc+2][lr+64] = b1.z; Bs[nxt][lc+3][lr+64] = b1.w;
            __syncthreads();
        }
    }

    // epilogue: s = exp(2*dot - 2), store, accumulate partial sums
    float rsum[8], csum[8];
#pragma unroll
    for (int i = 0; i < 8; i++) rsum[i] = 0.f;
#pragma unroll
    for (int j = 0; j < 8; j++) csum[j] = 0.f;

#pragma unroll
    for (int i = 0; i < 8; i++) {
        const int ri = rowBase + ((i < 4) ? (ty * 4 + i) : (64 + ty * 4 + i - 4));
        float sv[8];
#pragma unroll
        for (int j = 0; j < 8; j++) {
            float s = expf(fmaf(2.f, acc[i][j], -2.f));
            sv[j] = s;
            rsum[i] += s;
            csum[j] += s;
        }
        size_t rb = (size_t)ri * NCOLS + colBase;
        *(float4*)(g_S + rb + tx * 4)      = make_float4(sv[0], sv[1], sv[2], sv[3]);
        *(float4*)(g_S + rb + 64 + tx * 4) = make_float4(sv[4], sv[5], sv[6], sv[7]);
    }

    // row partial sums: reduce across tx (same-ty threads are a half-warp)
#pragma unroll
    for (int i = 0; i < 8; i++) {
        float v = rsum[i];
#pragma unroll
        for (int off = 1; off < 16; off <<= 1)
            v += __shfl_xor_sync(0xFFFFFFFFu, v, off, 16);
        if (tx == 0) {
            const int ri = rowBase + ((i < 4) ? (ty * 4 + i) : (64 + ty * 4 + i - 4));
            g_rowPart[blockIdx.x * MROWS + ri] = v;
        }
    }

    // column partial sums: reduce across ty via shared
    __syncthreads();   // protect sC vs last buffer reads? (sC separate, but cheap safety for reuse)
#pragma unroll
    for (int j = 0; j < 8; j++) {
        const int cj = (j < 4) ? (tx * 4 + j) : (64 + tx * 4 + j - 4);
        sC[ty][cj] = csum[j];
    }
    __syncthreads();
    if (tid < 128) {
        float v = 0.f;
#pragma unroll
        for (int r = 0; r < 16; r++) v += sC[r][tid];
        g_colPart[blockIdx.y * NCOLS + colBase + tid] = v;
    }
}

// ---------------- deterministic reduction of partial sums -> reciprocals ----------------
__global__ void reduce_sums_kernel() {
    int i = blockIdx.x * blockDim.x + threadIdx.x;
    if (i < MROWS) {
        float s = 0.f;
        for (int b = 0; b < NTILES; b++) s += g_rowPart[b * MROWS + i];
        g_invRow[i] = 1.0f / s;
    } else if (i < MROWS + NCOLS) {
        int c = i - MROWS;
        float s = 0.f;
        for (int b = 0; b < NTILES; b++) s += g_colPart[b * NCOLS + c];
        g_invCol[c] = 1.0f / s;
    }
}

// f = s*s*invR*invC, identical expression in every pass (bit-consistent).
__device__ __forceinline__ float4 fval4(float4 s, float invR, float4 ic) {
    float4 f;
    f.x = s.x * s.x * invR * ic.x;
    f.y = s.y * s.y * invR * ic.y;
    f.z = s.z * s.z * invR * ic.z;
    f.w = s.w * s.w * invR * ic.w;
    return f;
}

// ---------------- pass A: global max of f (read-only, coalesced, MLP=8) ----------------
__global__ void __launch_bounds__(256) max_kernel() {
    const float4* __restrict__ S4 = (const float4*)g_S;
    const float4* __restrict__ IC = (const float4*)g_invCol;
    size_t p0 = (size_t)blockIdx.x * 256 + threadIdx.x;
    float m = 0.f;
#pragma unroll
    for (int it = 0; it < SITER; it++) {
        size_t p = p0 + (size_t)it * (SGRID * 256);
        float4 s  = S4[p];
        float invR = g_invRow[p >> 11];       // 2048 float4 per row
        float4 ic = IC[p & 2047];
        float4 f = fval4(s, invR, ic);
        m = fmaxf(m, fmaxf(fmaxf(f.x, f.y), fmaxf(f.z, f.w)));
    }
    __shared__ float red[256];
    red[threadIdx.x] = m;
    __syncthreads();
    for (int s = 128; s > 0; s >>= 1) {
        if (threadIdx.x < s) red[threadIdx.x] = fmaxf(red[threadIdx.x], red[threadIdx.x + s]);
        __syncthreads();
    }
    if (threadIdx.x == 0) atomicMax(&g_maxbits, __float_as_uint(red[0]));
}

// ---------------- pass B: histogram of float-bit distance from max ----------------
__global__ void __launch_bounds__(256) hist_kernel() {
    __shared__ unsigned int h[NBINS];
    for (int t = threadIdx.x; t < NBINS; t += 256) h[t] = 0;
    __syncthreads();
    unsigned int mb = g_maxbits;
    const float4* __restrict__ S4 = (const float4*)g_S;
    const float4* __restrict__ IC = (const float4*)g_invCol;
    size_t p0 = (size_t)blockIdx.x * 256 + threadIdx.x;
#pragma unroll
    for (int it = 0; it < SITER; it++) {
        size_t p = p0 + (size_t)it * (SGRID * 256);
        float4 s  = S4[p];
        float invR = g_invRow[p >> 11];
        float4 ic = IC[p & 2047];
        float4 f = fval4(s, invR, ic);
        unsigned int d;
        d = mb - __float_as_uint(f.x); if (d < (NBINS << BINSHIFT)) atomicAdd(&h[d >> BINSHIFT], 1u);
        d = mb - __float_as_uint(f.y); if (d < (NBINS << BINSHIFT)) atomicAdd(&h[d >> BINSHIFT], 1u);
        d = mb - __float_as_uint(f.z); if (d < (NBINS << BINSHIFT)) atomicAdd(&h[d >> BINSHIFT], 1u);
        d = mb - __float_as_uint(f.w); if (d < (NBINS << BINSHIFT)) atomicAdd(&h[d >> BINSHIFT], 1u);
    }
    __syncthreads();
    for (int t = threadIdx.x; t < NBINS; t += 256)
        if (h[t]) atomicAdd(&g_hist[t], h[t]);
}

// ---------------- threshold scan ----------------
__global__ void threshold_kernel() {
    if (threadIdx.x == 0) {
        unsigned int cum = 0;
        int t = NBINS - 1;
        for (int b = 0; b < NBINS; b++) {
            cum += g_hist[b];
            if (cum >= TOPK) { t = b; break; }
        }
        g_thrbits = g_maxbits - (((unsigned int)(t + 1)) << BINSHIFT) + 1u;
    }
}

// ---------------- pass C: collect candidates above threshold ----------------
__global__ void __launch_bounds__(256) collect_kernel() {
    unsigned int thr = g_thrbits;
    const float4* __restrict__ S4 = (const float4*)g_S;
    const float4* __restrict__ IC = (const float4*)g_invCol;
    size_t p0 = (size_t)blockIdx.x * 256 + threadIdx.x;
#pragma unroll
    for (int it = 0; it < SITER; it++) {
        size_t p = p0 + (size_t)it * (SGRID * 256);
        float4 s  = S4[p];
        float invR = g_invRow[p >> 11];
        float4 ic = IC[p & 2047];
        float4 f = fval4(s, invR, ic);
        float vs[4] = {f.x, f.y, f.z, f.w};
#pragma unroll
        for (int e = 0; e < 4; e++) {
            unsigned int bits = __float_as_uint(vs[e]);
            if (bits >= thr) {
                unsigned int q = atomicAdd(&g_count, 1u);
                if (q < KCAND) {
                    g_cand_bits[q] = bits;
                    g_cand_idx[q]  = (unsigned int)(p * 4 + e);
                }
            }
        }
    }
}

// ---------------- single-block exact top-K by rank counting ----------------
__global__ void __launch_bounds__(1024) select_kernel(float* __restrict__ out) {
    __shared__ unsigned int sb[KCAND];
    __shared__ unsigned int si[KCAND];
    int n = (int)min(g_count, (unsigned int)KCAND);
    for (int i = threadIdx.x; i < n; i += 1024) {
        sb[i] = g_cand_bits[i];
        si[i] = g_cand_idx[i];
    }
    __syncthreads();
    for (int c = threadIdx.x; c < n; c += 1024) {
        unsigned int vb = sb[c], vi = si[c];
        int r = 0;
        for (int d = 0; d < n; d++) {
            unsigned int db = sb[d];
            r += (db > vb) || (db == vb && si[d] < vi);   // value desc, index asc (top_k tie-break)
        }
        if (r < TOPK) {
            out[r]            = (float)(vi >> 13);     // ref index = flat / 8192
            out[TOPK + r]     = (float)(vi & 8191u);   // src index = flat % 8192
            out[2 * TOPK + r] = __uint_as_float(vb);   // score
        }
    }
}

// ---------------- launch ----------------
extern "C" void kernel_launch(void* const* d_in, const int* in_sizes, int n_in,
                              void* d_out, int out_size) {
    const float* ref = (const float*)d_in[0];
    const float* src = (const float*)d_in[1];
    float* out = (float*)d_out;

    init_kernel<<<8, 256>>>();
    gemm_exp_kernel<<<dim3(64, 64), 256>>>(ref, src);
    reduce_sums_kernel<<<64, 256>>>();
    max_kernel<<<SGRID, 256>>>();
    hist_kernel<<<SGRID, 256>>>();
    threshold_kernel<<<1, 32>>>();
    collect_kernel<<<SGRID, 256>>>();
    select_kernel<<<1, 1024>>>(out);
}